// round 13
// baseline (speedup 1.0000x reference)
#include <cuda_runtime.h>

#define BB     64
#define CC     256
#define HH     56
#define WW     56
#define HW     3136
#define NROWS  (BB*CC)        // 16384
#define TOPK   38
#define MAIN4  768            // 784 float4/row = 6*128 + 16
#define HWQ    392            // float4 per half-row
#define BPB    19             // blocks per batch in k23 (76 tasks / 4 warps)

__device__ float g_sums[NROWS];
__device__ int   g_amax[NROWS];

__device__ __forceinline__ void quad_max(float4 v, int p, float& mval, int& midx) {
    const float m4 = fmaxf(fmaxf(v.x, v.y), fmaxf(v.z, v.w));
    if (m4 > mval) {
        mval = m4;
        midx = p + ((v.x == m4) ? 0 : (v.y == m4) ? 1 : (v.z == m4) ? 2 : 3);
    }
}

// ---------------------------------------------------------------------------
// K1: warp-per-row, unroll-by-4, pure streaming (ldcs/stcs) — frozen.
// Measured at the mixed-R/W HBM ceiling (74% DRAM across 5 configs).
// ---------------------------------------------------------------------------
__global__ __launch_bounds__(256) void k1_reduce_copy(const float* __restrict__ x,
                                                      float* __restrict__ out) {
    const int warp = threadIdx.x >> 5;
    const int lane = threadIdx.x & 31;
    const int row  = blockIdx.x * 8 + warp;

    const float4* __restrict__ xr  = (const float4*)(x   + (size_t)row * HW);
    float4*       __restrict__ orr = (float4*)      (out + (size_t)row * HW);

    float s0 = 0.f, s1 = 0.f, s2 = 0.f, s3 = 0.f;
    float mval = -3.402823466e38f;
    int   midx = 0;

    #pragma unroll
    for (int base = 0; base < MAIN4; base += 128) {
        const int i0 = base + lane;
        float4 a = __ldcs(&xr[i0]);
        float4 b = __ldcs(&xr[i0 + 32]);
        float4 c = __ldcs(&xr[i0 + 64]);
        float4 d = __ldcs(&xr[i0 + 96]);
        __stcs(&orr[i0],      a);
        __stcs(&orr[i0 + 32], b);
        __stcs(&orr[i0 + 64], c);
        __stcs(&orr[i0 + 96], d);
        s0 += a.x + a.y + a.z + a.w;
        s1 += b.x + b.y + b.z + b.w;
        s2 += c.x + c.y + c.z + c.w;
        s3 += d.x + d.y + d.z + d.w;
        quad_max(a, (i0)      << 2, mval, midx);
        quad_max(b, (i0 + 32) << 2, mval, midx);
        quad_max(c, (i0 + 64) << 2, mval, midx);
        quad_max(d, (i0 + 96) << 2, mval, midx);
    }
    if (lane < 16) {
        const int i0 = MAIN4 + lane;
        float4 a = __ldcs(&xr[i0]);
        __stcs(&orr[i0], a);
        s0 += a.x + a.y + a.z + a.w;
        quad_max(a, i0 << 2, mval, midx);
    }

    float sum = (s0 + s1) + (s2 + s3);
    #pragma unroll
    for (int off = 16; off > 0; off >>= 1) {
        sum += __shfl_down_sync(0xffffffffu, sum, off);
        float ov = __shfl_down_sync(0xffffffffu, mval, off);
        int   oi = __shfl_down_sync(0xffffffffu, midx, off);
        if (ov > mval || (ov == mval && oi < midx)) { mval = ov; midx = oi; }
    }
    if (lane == 0) {
        g_sums[row] = sum;
        g_amax[row] = midx;
    }
    cudaTriggerProgrammaticLaunchCompletion();
}

// ---------------------------------------------------------------------------
// K23: each block REDUNDANTLY computes its own batch's SE + top-38 (no
// cross-block communication), then applies 4 half-row tasks. Grid = 64*19
// blocks of 128. Weights prefetched before the PDL dependency sync.
// ---------------------------------------------------------------------------
__global__ __launch_bounds__(128) void k23_select_apply(const float* __restrict__ x,
                                                        float* __restrict__ out,
                                                        const float* __restrict__ w1,
                                                        const float* __restrict__ w2) {
    const int tid  = threadIdx.x;
    const int warp = tid >> 5;
    const int lane = tid & 31;
    const int b    = blockIdx.x / BPB;
    const int blk  = blockIdx.x % BPB;

    // fc1 mapping: 8 threads per hidden unit d, each covering 32 channels.
    const int d  = tid >> 3;          // 0..15
    const int p8 = tid & 7;           // 0..7
    const int c0 = p8 * 32;

    // ---- prefetch weights (independent of K1) before the dependency sync --
    float w1v[32];
    #pragma unroll
    for (int k = 0; k < 32; k++) w1v[k] = __ldg(&w1[d * CC + c0 + k]);
    float w2lo[16], w2hi[16];
    #pragma unroll
    for (int k = 0; k < 16; k++) w2lo[k] = __ldg(&w2[tid * 16 + k]);
    #pragma unroll
    for (int k = 0; k < 16; k++) w2hi[k] = __ldg(&w2[(tid + 128) * 16 + k]);

    cudaGridDependencySynchronize();   // K1's g_sums/g_amax now visible

    __shared__ float s_pooled[CC];
    __shared__ float s_hidden[16];
    __shared__ float s_M[CC];
    __shared__ int   s_selrow[TOPK];

    s_pooled[tid]       = g_sums[b * CC + tid]       * (1.0f / (float)HW);
    s_pooled[tid + 128] = g_sums[b * CC + tid + 128] * (1.0f / (float)HW);
    __syncthreads();

    // fc1 + relu: reduce over the 8-lane group (octet-aligned => shfl_xor ok)
    {
        float acc = 0.0f;
        #pragma unroll
        for (int k = 0; k < 32; k++) acc += s_pooled[c0 + k] * w1v[k];
        acc += __shfl_xor_sync(0xffffffffu, acc, 4);
        acc += __shfl_xor_sync(0xffffffffu, acc, 2);
        acc += __shfl_xor_sync(0xffffffffu, acc, 1);
        if (p8 == 0) s_hidden[d] = fmaxf(acc, 0.0f);
    }
    __syncthreads();

    // fc2 + sigmoid for channels tid and tid+128
    {
        float acca = 0.0f, accb = 0.0f;
        #pragma unroll
        for (int k = 0; k < 16; k++) {
            const float h = s_hidden[k];
            acca += h * w2lo[k];
            accb += h * w2hi[k];
        }
        s_M[tid]       = 1.0f / (1.0f + expf(-acca));
        s_M[tid + 128] = 1.0f / (1.0f + expf(-accb));
    }
    __syncthreads();

    // exact rank-based top-38 (first-index tie-break), both channels
    {
        const float ma = s_M[tid];
        const float mb = s_M[tid + 128];
        int ca = 0, cb = 0;
        #pragma unroll 8
        for (int j = 0; j < CC; j++) {
            const float mj = s_M[j];
            ca += (mj > ma) || (mj == ma && j < tid);
            cb += (mj > mb) || (mj == mb && j < tid + 128);
        }
        if (ca < TOPK) s_selrow[ca] = tid;
        if (cb < TOPK) s_selrow[cb] = tid + 128;
    }
    __syncthreads();

    // ---- apply: 4 half-row tasks for this block --------------------------
    const int task = blk * 4 + warp;          // 0..75 within batch
    const int selb = task >> 1;               // 0..37
    const int part = task & 1;

    const int row  = b * CC + s_selrow[selb];
    const int aidx = g_amax[row];
    const int mh = aidx / WW;
    const int mw = aidx % WW;
    const int bh1 = max(mh - 2, 0), bh2 = min(mh + 2, HH - 1);
    const int bw1 = max(mw - 2, 0), bw2 = min(mw + 2, WW - 1);
    const int box = (bh2 - bh1 + 1) * (bw2 - bw1 + 1);
    const float lam = (float)HW / (float)(HW - box);

    const float4* __restrict__ xr  = (const float4*)(x   + (size_t)row * HW);
    float4*       __restrict__ orr = (float4*)      (out + (size_t)row * HW);
    const int q0 = part * HWQ;                // [q0, q0+392)

    // Front-batch the whole half-row: 392 = 12*32 + 8.
    float4 v[12];
    #pragma unroll
    for (int k = 0; k < 12; k++) v[k] = __ldcs(&xr[q0 + k * 32 + lane]);
    float4 vt;
    const bool has_tail = (lane < 8);
    if (has_tail) vt = __ldcs(&xr[q0 + 384 + lane]);

    #pragma unroll
    for (int k = 0; k < 12; k++) {
        const int i0 = q0 + k * 32 + lane;
        const int p  = i0 << 2;
        const int r  = p / WW;
        const int cc = p % WW;                // WW % 4 == 0: same image row
        const bool rin = (r >= bh1) && (r <= bh2);
        float4 o;
        o.x = (rin && cc     >= bw1 && cc     <= bw2) ? 0.0f : v[k].x * lam;
        o.y = (rin && cc + 1 >= bw1 && cc + 1 <= bw2) ? 0.0f : v[k].y * lam;
        o.z = (rin && cc + 2 >= bw1 && cc + 2 <= bw2) ? 0.0f : v[k].z * lam;
        o.w = (rin && cc + 3 >= bw1 && cc + 3 <= bw2) ? 0.0f : v[k].w * lam;
        __stcs(&orr[i0], o);
    }
    if (has_tail) {
        const int i0 = q0 + 384 + lane;
        const int p  = i0 << 2;
        const int r  = p / WW;
        const int cc = p % WW;
        const bool rin = (r >= bh1) && (r <= bh2);
        float4 o;
        o.x = (rin && cc     >= bw1 && cc     <= bw2) ? 0.0f : vt.x * lam;
        o.y = (rin && cc + 1 >= bw1 && cc + 1 <= bw2) ? 0.0f : vt.y * lam;
        o.z = (rin && cc + 2 >= bw1 && cc + 2 <= bw2) ? 0.0f : vt.z * lam;
        o.w = (rin && cc + 3 >= bw1 && cc + 3 <= bw2) ? 0.0f : vt.w * lam;
        __stcs(&orr[i0], o);
    }
}

// ---------------------------------------------------------------------------
extern "C" void kernel_launch(void* const* d_in, const int* in_sizes, int n_in,
                              void* d_out, int out_size) {
    const float* x  = (const float*)d_in[0];
    const float* w1 = (const float*)d_in[1];
    const float* w2 = (const float*)d_in[2];
    float* out = (float*)d_out;

    k1_reduce_copy<<<NROWS / 8, 256>>>(x, out);   // 2048 blocks

    cudaLaunchAttribute attr[1];
    attr[0].id = cudaLaunchAttributeProgrammaticStreamSerialization;
    attr[0].val.programmaticStreamSerializationAllowed = 1;

    cudaLaunchConfig_t cfg = {};
    cfg.gridDim  = dim3(BB * BPB, 1, 1);          // 1216 blocks
    cfg.blockDim = dim3(128, 1, 1);
    cfg.attrs    = attr;
    cfg.numAttrs = 1;
    cudaLaunchKernelEx(&cfg, k23_select_apply, x, out, w1, w2);
}

// round 14
// speedup vs baseline: 1.3471x; 1.3471x over previous
#include <cuda_runtime.h>

#define BB     64
#define CC     256
#define HH     56
#define WW     56
#define HW     3136
#define NROWS  (BB*CC)        // 16384
#define TOPK   38
#define NSEL   (BB*TOPK)      // 2432
#define MAIN4  768            // 784 float4/row = 6*128 + 16
#define HWQ    392            // float4 per half-row

__device__ float g_sums[NROWS];
__device__ int   g_amax[NROWS];
__device__ int4  g_task[NSEL];   // {row, aidx, lam_bits, 0}

__device__ __forceinline__ void quad_max(float4 v, int p, float& mval, int& midx) {
    const float m4 = fmaxf(fmaxf(v.x, v.y), fmaxf(v.z, v.w));
    if (m4 > mval) {
        mval = m4;
        midx = p + ((v.x == m4) ? 0 : (v.y == m4) ? 1 : (v.z == m4) ? 2 : 3);
    }
}

// ---------------------------------------------------------------------------
// K1: warp-per-row, unroll-by-4. Streaming ldcs reads of x; DEFAULT
// (write-back) stores of out — R2 measured this 0.5us faster than stcs and
// it leaves out hot in L2 for K3's re-read.
// ---------------------------------------------------------------------------
__global__ __launch_bounds__(256) void k1_reduce_copy(const float* __restrict__ x,
                                                      float* __restrict__ out) {
    const int warp = threadIdx.x >> 5;
    const int lane = threadIdx.x & 31;
    const int row  = blockIdx.x * 8 + warp;

    const float4* __restrict__ xr  = (const float4*)(x   + (size_t)row * HW);
    float4*       __restrict__ orr = (float4*)      (out + (size_t)row * HW);

    float s0 = 0.f, s1 = 0.f, s2 = 0.f, s3 = 0.f;
    float mval = -3.402823466e38f;
    int   midx = 0;

    #pragma unroll
    for (int base = 0; base < MAIN4; base += 128) {
        const int i0 = base + lane;
        float4 a = __ldcs(&xr[i0]);
        float4 b = __ldcs(&xr[i0 + 32]);
        float4 c = __ldcs(&xr[i0 + 64]);
        float4 d = __ldcs(&xr[i0 + 96]);
        orr[i0]      = a;
        orr[i0 + 32] = b;
        orr[i0 + 64] = c;
        orr[i0 + 96] = d;
        s0 += a.x + a.y + a.z + a.w;
        s1 += b.x + b.y + b.z + b.w;
        s2 += c.x + c.y + c.z + c.w;
        s3 += d.x + d.y + d.z + d.w;
        quad_max(a, (i0)      << 2, mval, midx);
        quad_max(b, (i0 + 32) << 2, mval, midx);
        quad_max(c, (i0 + 64) << 2, mval, midx);
        quad_max(d, (i0 + 96) << 2, mval, midx);
    }
    if (lane < 16) {
        const int i0 = MAIN4 + lane;
        float4 a = __ldcs(&xr[i0]);
        orr[i0] = a;
        s0 += a.x + a.y + a.z + a.w;
        quad_max(a, i0 << 2, mval, midx);
    }

    float sum = (s0 + s1) + (s2 + s3);
    #pragma unroll
    for (int off = 16; off > 0; off >>= 1) {
        sum += __shfl_down_sync(0xffffffffu, sum, off);
        float ov = __shfl_down_sync(0xffffffffu, mval, off);
        int   oi = __shfl_down_sync(0xffffffffu, midx, off);
        if (ov > mval || (ov == mval && oi < midx)) { mval = ov; midx = oi; }
    }
    if (lane == 0) {
        g_sums[row] = sum;
        g_amax[row] = midx;
    }
    cudaTriggerProgrammaticLaunchCompletion();
}

// ---------------------------------------------------------------------------
// K2: one block per batch. PDL weight prefetch before the dependency sync,
// SE + exact top-38, packed task descriptors {row, aidx, lam}.
// ---------------------------------------------------------------------------
__global__ __launch_bounds__(256) void k2_se_topk(const float* __restrict__ w1,
                                                  const float* __restrict__ w2) {
    const int b = blockIdx.x;
    const int t = threadIdx.x;
    const int d    = t >> 4;
    const int part = t & 15;
    const int c0   = part * 16;

    float w1v[16], w2v[16];
    #pragma unroll
    for (int k = 0; k < 16; k++) w1v[k] = __ldg(&w1[d * CC + c0 + k]);
    #pragma unroll
    for (int k = 0; k < 16; k++) w2v[k] = __ldg(&w2[t * 16 + k]);

    cudaGridDependencySynchronize();   // K1's g_sums/g_amax now visible

    __shared__ float s_pooled[CC];
    __shared__ float s_hidden[16];
    __shared__ float s_M[CC];

    s_pooled[t] = g_sums[b * CC + t] * (1.0f / (float)HW);
    __syncthreads();

    {
        float acc = 0.0f;
        #pragma unroll
        for (int k = 0; k < 16; k++) acc += s_pooled[c0 + k] * w1v[k];
        #pragma unroll
        for (int off = 8; off > 0; off >>= 1)
            acc += __shfl_xor_sync(0xffffffffu, acc, off);
        if (part == 0) s_hidden[d] = fmaxf(acc, 0.0f);
    }
    __syncthreads();

    {
        float acc = 0.0f;
        #pragma unroll
        for (int k = 0; k < 16; k++) acc += s_hidden[k] * w2v[k];
        s_M[t] = 1.0f / (1.0f + expf(-acc));
    }
    __syncthreads();

    const float m = s_M[t];
    int cnt = 0;
    for (int j = 0; j < CC; j++) {
        const float mj = s_M[j];
        cnt += (mj > m) || (mj == m && j < t);
    }
    if (cnt < TOPK) {
        const int row  = b * CC + t;
        const int aidx = g_amax[row];
        const int mh = aidx / WW;
        const int mw = aidx % WW;
        const int h1  = max(mh - 2, 0), h2  = min(mh + 2, HH - 1);
        const int w1b = max(mw - 2, 0), w2b = min(mw + 2, WW - 1);
        const int box = (h2 - h1 + 1) * (w2b - w1b + 1);
        const float lam = (float)HW / (float)(HW - box);
        g_task[b * TOPK + cnt] = make_int4(row, aidx, __float_as_int(lam), 0);
    }
    cudaTriggerProgrammaticLaunchCompletion();
}

// ---------------------------------------------------------------------------
// K3: half-row per warp, all loads front-batched (MLP ~13). Reads the
// selected rows from OUT (identical bytes; ~60% still L2-resident from K1's
// write-back stores => 234cyc hits instead of 577cyc DRAM misses).
// ---------------------------------------------------------------------------
__global__ __launch_bounds__(128) void k3_apply(float* __restrict__ out) {
    cudaGridDependencySynchronize();   // K2's g_task now visible

    const int warp = threadIdx.x >> 5;
    const int lane = threadIdx.x & 31;
    const int gw   = blockIdx.x * 4 + warp;
    const int sel  = gw >> 1;
    const int part = gw & 1;

    const int4 tk  = g_task[sel];
    const int row  = tk.x;
    const int aidx = tk.y;
    const float lam = __int_as_float(tk.z);
    const int mh = aidx / WW;
    const int mw = aidx % WW;
    const int h1  = max(mh - 2, 0), h2  = min(mh + 2, HH - 1);
    const int w1b = max(mw - 2, 0), w2b = min(mw + 2, WW - 1);

    float4* __restrict__ orr = (float4*)(out + (size_t)row * HW);
    const int q0 = part * HWQ;                // [q0, q0+392)

    // Front-batch the whole half-row: 392 = 12*32 + 8.
    float4 v[12];
    #pragma unroll
    for (int k = 0; k < 12; k++) v[k] = orr[q0 + k * 32 + lane];
    float4 vt;
    const bool has_tail = (lane < 8);
    if (has_tail) vt = orr[q0 + 384 + lane];

    #pragma unroll
    for (int k = 0; k < 12; k++) {
        const int i0 = q0 + k * 32 + lane;
        const int p  = i0 << 2;
        const int r  = p / WW;
        const int c0 = p % WW;                // WW % 4 == 0: same image row
        const bool rin = (r >= h1) && (r <= h2);
        float4 o;
        o.x = (rin && c0     >= w1b && c0     <= w2b) ? 0.0f : v[k].x * lam;
        o.y = (rin && c0 + 1 >= w1b && c0 + 1 <= w2b) ? 0.0f : v[k].y * lam;
        o.z = (rin && c0 + 2 >= w1b && c0 + 2 <= w2b) ? 0.0f : v[k].z * lam;
        o.w = (rin && c0 + 3 >= w1b && c0 + 3 <= w2b) ? 0.0f : v[k].w * lam;
        orr[i0] = o;
    }
    if (has_tail) {
        const int i0 = q0 + 384 + lane;
        const int p  = i0 << 2;
        const int r  = p / WW;
        const int c0 = p % WW;
        const bool rin = (r >= h1) && (r <= h2);
        float4 o;
        o.x = (rin && c0     >= w1b && c0     <= w2b) ? 0.0f : vt.x * lam;
        o.y = (rin && c0 + 1 >= w1b && c0 + 1 <= w2b) ? 0.0f : vt.y * lam;
        o.z = (rin && c0 + 2 >= w1b && c0 + 2 <= w2b) ? 0.0f : vt.z * lam;
        o.w = (rin && c0 + 3 >= w1b && c0 + 3 <= w2b) ? 0.0f : vt.w * lam;
        orr[i0] = o;
    }
}

// ---------------------------------------------------------------------------
extern "C" void kernel_launch(void* const* d_in, const int* in_sizes, int n_in,
                              void* d_out, int out_size) {
    const float* x  = (const float*)d_in[0];
    const float* w1 = (const float*)d_in[1];
    const float* w2 = (const float*)d_in[2];
    float* out = (float*)d_out;

    cudaLaunchAttribute attr[1];
    attr[0].id = cudaLaunchAttributeProgrammaticStreamSerialization;
    attr[0].val.programmaticStreamSerializationAllowed = 1;

    k1_reduce_copy<<<NROWS / 8, 256>>>(x, out);   // 2048 blocks

    {   // K2 with PDL
        cudaLaunchConfig_t cfg = {};
        cfg.gridDim  = dim3(BB, 1, 1);
        cfg.blockDim = dim3(256, 1, 1);
        cfg.attrs    = attr;
        cfg.numAttrs = 1;
        cudaLaunchKernelEx(&cfg, k2_se_topk, w1, w2);
    }
    {   // K3 with PDL: NSEL*2 half-row tasks, 4 warps/block
        cudaLaunchConfig_t cfg = {};
        cfg.gridDim  = dim3(NSEL / 2, 1, 1);      // 1216 blocks
        cfg.blockDim = dim3(128, 1, 1);
        cfg.attrs    = attr;
        cfg.numAttrs = 1;
        cudaLaunchKernelEx(&cfg, k3_apply, out);
    }
}

// round 15
// speedup vs baseline: 1.3695x; 1.0166x over previous
#include <cuda_runtime.h>

#define BB     64
#define CC     256
#define HH     56
#define WW     56
#define HW     3136
#define NROWS  (BB*CC)        // 16384
#define TOPK   38
#define NSEL   (BB*TOPK)      // 2432
#define HWQ    392            // float4 per half-row

__device__ float g_sums[NROWS];
__device__ int   g_amax[NROWS];
__device__ int4  g_task[NSEL];       // {row, aidx, lam_bits, 0}
__device__ unsigned int g_bc[BB];    // per-batch completion counters (0-init, self-reset)

__device__ __forceinline__ void quad_max(float4 v, int p, float& mval, int& midx) {
    const float m4 = fmaxf(fmaxf(v.x, v.y), fmaxf(v.z, v.w));
    if (m4 > mval) {
        mval = m4;
        midx = p + ((v.x == m4) ? 0 : (v.y == m4) ? 1 : (v.z == m4) ? 2 : 3);
    }
}

// ---------------------------------------------------------------------------
// K1 (fused): per-row reduce + copy + per-batch SE/top-k selection.
// Order per block: (1) load whole row into registers, (2) reduce + publish
// g_sums/g_amax, (3) CHEAP fence (no big stores in flight yet) + per-batch
// counter; last of the 32 blocks of a batch computes SE + top-38 and emits
// packed g_task entries, (4) all blocks issue their streaming stores.
// ---------------------------------------------------------------------------
__global__ __launch_bounds__(256) void k1_fused(const float* __restrict__ x,
                                                float* __restrict__ out,
                                                const float* __restrict__ w1,
                                                const float* __restrict__ w2) {
    const int tid   = threadIdx.x;
    const int warp  = tid >> 5;
    const int lane  = tid & 31;
    const int row   = blockIdx.x * 8 + warp;
    const int batch = blockIdx.x >> 5;          // 32 blocks per batch

    const float4* __restrict__ xr  = (const float4*)(x   + (size_t)row * HW);
    float4*       __restrict__ orr = (float4*)      (out + (size_t)row * HW);

    // ---- (1) load the whole row into registers (784 = 24*32 + 16) --------
    float4 v[24];
    #pragma unroll
    for (int k = 0; k < 24; k++) v[k] = __ldcs(&xr[k * 32 + lane]);
    float4 vt;
    const bool has_tail = (lane < 16);
    if (has_tail) vt = __ldcs(&xr[768 + lane]);

    // ---- (2) reduce: sum + argmax (first-index tie-break) -----------------
    float s0 = 0.f, s1 = 0.f, s2 = 0.f, s3 = 0.f;
    float mval = -3.402823466e38f;
    int   midx = 0;
    #pragma unroll
    for (int k = 0; k < 24; k++) {
        const float4 a = v[k];
        if ((k & 3) == 0) s0 += a.x + a.y + a.z + a.w;
        if ((k & 3) == 1) s1 += a.x + a.y + a.z + a.w;
        if ((k & 3) == 2) s2 += a.x + a.y + a.z + a.w;
        if ((k & 3) == 3) s3 += a.x + a.y + a.z + a.w;
        quad_max(a, (k * 32 + lane) << 2, mval, midx);
    }
    if (has_tail) {
        s0 += vt.x + vt.y + vt.z + vt.w;
        quad_max(vt, (768 + lane) << 2, mval, midx);
    }
    float sum = (s0 + s1) + (s2 + s3);
    #pragma unroll
    for (int off = 16; off > 0; off >>= 1) {
        sum += __shfl_down_sync(0xffffffffu, sum, off);
        float ov = __shfl_down_sync(0xffffffffu, mval, off);
        int   oi = __shfl_down_sync(0xffffffffu, midx, off);
        if (ov > mval || (ov == mval && oi < midx)) { mval = ov; midx = oi; }
    }
    if (lane == 0) {
        g_sums[row] = sum;
        g_amax[row] = midx;
    }

    // ---- (3) cheap publish + per-batch finisher election ------------------
    __shared__ int s_fin;
    __syncthreads();
    __threadfence();   // only the 16 tiny g_sums/g_amax stores are in flight
    if (tid == 0) s_fin = (atomicAdd(&g_bc[batch], 1u) == 31u) ? 1 : 0;
    __syncthreads();

    if (s_fin) {
        __threadfence();   // acquire: other blocks' g_sums/g_amax visible

        __shared__ float s_pooled[CC];
        __shared__ float s_hidden[16];
        __shared__ float s_M[CC];

        const int t    = tid;
        const int d    = t >> 4;
        const int part = t & 15;
        const int c0   = part * 16;

        s_pooled[t] = g_sums[batch * CC + t] * (1.0f / (float)HW);
        __syncthreads();

        {   // fc1 + relu: 16-thread group per hidden unit, shfl-xor reduce
            float acc = 0.0f;
            const float* __restrict__ w1r = w1 + d * CC + c0;
            #pragma unroll
            for (int k = 0; k < 16; k++) acc += s_pooled[c0 + k] * __ldg(&w1r[k]);
            #pragma unroll
            for (int off = 8; off > 0; off >>= 1)
                acc += __shfl_xor_sync(0xffffffffu, acc, off);
            if (part == 0) s_hidden[d] = fmaxf(acc, 0.0f);
        }
        __syncthreads();

        {   // fc2 + sigmoid
            float acc = 0.0f;
            const float* __restrict__ w2r = w2 + t * 16;
            #pragma unroll
            for (int k = 0; k < 16; k++) acc += s_hidden[k] * __ldg(&w2r[k]);
            s_M[t] = 1.0f / (1.0f + expf(-acc));
        }
        __syncthreads();

        // exact rank-based top-38, packed task emit
        const float m = s_M[t];
        int cnt = 0;
        for (int j = 0; j < CC; j++) {
            const float mj = s_M[j];
            cnt += (mj > m) || (mj == m && j < t);
        }
        if (cnt < TOPK) {
            const int srow = batch * CC + t;
            const int aidx = g_amax[srow];
            const int mh = aidx / WW;
            const int mw = aidx % WW;
            const int bh1 = max(mh - 2, 0), bh2 = min(mh + 2, HH - 1);
            const int bw1 = max(mw - 2, 0), bw2 = min(mw + 2, WW - 1);
            const int box = (bh2 - bh1 + 1) * (bw2 - bw1 + 1);
            const float lam = (float)HW / (float)(HW - box);
            g_task[batch * TOPK + cnt] = make_int4(srow, aidx, __float_as_int(lam), 0);
        }
        if (tid == 0) g_bc[batch] = 0u;   // self-reset for next graph replay
    }

    // ---- (4) streaming stores of the copied row ---------------------------
    #pragma unroll
    for (int k = 0; k < 24; k++) __stcs(&orr[k * 32 + lane], v[k]);
    if (has_tail) __stcs(&orr[768 + lane], vt);
}

// ---------------------------------------------------------------------------
// K3: half-row per warp, all loads front-batched (MLP ~13), streaming
// ldcs/stcs (proven R10 body). Single packed-task load.
// ---------------------------------------------------------------------------
__global__ __launch_bounds__(128) void k3_apply(const float* __restrict__ x,
                                                float* __restrict__ out) {
    cudaGridDependencySynchronize();   // K1's g_task now visible

    const int warp = threadIdx.x >> 5;
    const int lane = threadIdx.x & 31;
    const int gw   = blockIdx.x * 4 + warp;
    const int sel  = gw >> 1;
    const int part = gw & 1;

    const int4 tk  = g_task[sel];
    const int row  = tk.x;
    const int aidx = tk.y;
    const float lam = __int_as_float(tk.z);
    const int mh = aidx / WW;
    const int mw = aidx % WW;
    const int h1  = max(mh - 2, 0), h2  = min(mh + 2, HH - 1);
    const int w1b = max(mw - 2, 0), w2b = min(mw + 2, WW - 1);

    const float4* __restrict__ xr  = (const float4*)(x   + (size_t)row * HW);
    float4*       __restrict__ orr = (float4*)      (out + (size_t)row * HW);
    const int q0 = part * HWQ;                // [q0, q0+392)

    // Front-batch the whole half-row: 392 = 12*32 + 8.
    float4 v[12];
    #pragma unroll
    for (int k = 0; k < 12; k++) v[k] = __ldcs(&xr[q0 + k * 32 + lane]);
    float4 vt;
    const bool has_tail = (lane < 8);
    if (has_tail) vt = __ldcs(&xr[q0 + 384 + lane]);

    #pragma unroll
    for (int k = 0; k < 12; k++) {
        const int i0 = q0 + k * 32 + lane;
        const int p  = i0 << 2;
        const int r  = p / WW;
        const int c0 = p % WW;                // WW % 4 == 0: same image row
        const bool rin = (r >= h1) && (r <= h2);
        float4 o;
        o.x = (rin && c0     >= w1b && c0     <= w2b) ? 0.0f : v[k].x * lam;
        o.y = (rin && c0 + 1 >= w1b && c0 + 1 <= w2b) ? 0.0f : v[k].y * lam;
        o.z = (rin && c0 + 2 >= w1b && c0 + 2 <= w2b) ? 0.0f : v[k].z * lam;
        o.w = (rin && c0 + 3 >= w1b && c0 + 3 <= w2b) ? 0.0f : v[k].w * lam;
        __stcs(&orr[i0], o);
    }
    if (has_tail) {
        const int i0 = q0 + 384 + lane;
        const int p  = i0 << 2;
        const int r  = p / WW;
        const int c0 = p % WW;
        const bool rin = (r >= h1) && (r <= h2);
        float4 o;
        o.x = (rin && c0     >= w1b && c0     <= w2b) ? 0.0f : vt.x * lam;
        o.y = (rin && c0 + 1 >= w1b && c0 + 1 <= w2b) ? 0.0f : vt.y * lam;
        o.z = (rin && c0 + 2 >= w1b && c0 + 2 <= w2b) ? 0.0f : vt.z * lam;
        o.w = (rin && c0 + 3 >= w1b && c0 + 3 <= w2b) ? 0.0f : vt.w * lam;
        __stcs(&orr[i0], o);
    }
}

// ---------------------------------------------------------------------------
extern "C" void kernel_launch(void* const* d_in, const int* in_sizes, int n_in,
                              void* d_out, int out_size) {
    const float* x  = (const float*)d_in[0];
    const float* w1 = (const float*)d_in[1];
    const float* w2 = (const float*)d_in[2];
    float* out = (float*)d_out;

    k1_fused<<<NROWS / 8, 256>>>(x, out, w1, w2);   // 2048 blocks (K1 + per-batch K2)

    cudaLaunchAttribute attr[1];
    attr[0].id = cudaLaunchAttributeProgrammaticStreamSerialization;
    attr[0].val.programmaticStreamSerializationAllowed = 1;

    cudaLaunchConfig_t cfg = {};
    cfg.gridDim  = dim3(NSEL / 2, 1, 1);            // 1216 blocks
    cfg.blockDim = dim3(128, 1, 1);
    cfg.attrs    = attr;
    cfg.numAttrs = 1;
    cudaLaunchKernelEx(&cfg, k3_apply, x, out);
}

// round 16
// speedup vs baseline: 1.3840x; 1.0105x over previous
#include <cuda_runtime.h>

#define BB     64
#define CC     256
#define HH     56
#define WW     56
#define HW     3136
#define NROWS  (BB*CC)        // 16384
#define TOPK   38
#define NSEL   (BB*TOPK)      // 2432
#define MAIN4  768            // 784 float4/row = 6*128 + 16
#define QW     196            // float4 per quarter-row

__device__ float g_sums[NROWS];
__device__ int   g_amax[NROWS];
__device__ int4  g_task[NSEL];   // {row, aidx, lam_bits, 0}

__device__ __forceinline__ void quad_max(float4 v, int p, float& mval, int& midx) {
    const float m4 = fmaxf(fmaxf(v.x, v.y), fmaxf(v.z, v.w));
    if (m4 > mval) {
        mval = m4;
        midx = p + ((v.x == m4) ? 0 : (v.y == m4) ? 1 : (v.z == m4) ? 2 : 3);
    }
}

// ---------------------------------------------------------------------------
// K1: warp-per-row, unroll-by-4, pure streaming (ldcs/stcs), no fences.
// Measured at the mixed-R/W HBM ceiling (74% DRAM across 6 configs) — frozen.
// ---------------------------------------------------------------------------
__global__ __launch_bounds__(256) void k1_reduce_copy(const float* __restrict__ x,
                                                      float* __restrict__ out) {
    const int warp = threadIdx.x >> 5;
    const int lane = threadIdx.x & 31;
    const int row  = blockIdx.x * 8 + warp;

    const float4* __restrict__ xr  = (const float4*)(x   + (size_t)row * HW);
    float4*       __restrict__ orr = (float4*)      (out + (size_t)row * HW);

    float s0 = 0.f, s1 = 0.f, s2 = 0.f, s3 = 0.f;
    float mval = -3.402823466e38f;
    int   midx = 0;

    #pragma unroll
    for (int base = 0; base < MAIN4; base += 128) {
        const int i0 = base + lane;
        float4 a = __ldcs(&xr[i0]);
        float4 b = __ldcs(&xr[i0 + 32]);
        float4 c = __ldcs(&xr[i0 + 64]);
        float4 d = __ldcs(&xr[i0 + 96]);
        __stcs(&orr[i0],      a);
        __stcs(&orr[i0 + 32], b);
        __stcs(&orr[i0 + 64], c);
        __stcs(&orr[i0 + 96], d);
        s0 += a.x + a.y + a.z + a.w;
        s1 += b.x + b.y + b.z + b.w;
        s2 += c.x + c.y + c.z + c.w;
        s3 += d.x + d.y + d.z + d.w;
        quad_max(a, (i0)      << 2, mval, midx);
        quad_max(b, (i0 + 32) << 2, mval, midx);
        quad_max(c, (i0 + 64) << 2, mval, midx);
        quad_max(d, (i0 + 96) << 2, mval, midx);
    }
    if (lane < 16) {
        const int i0 = MAIN4 + lane;
        float4 a = __ldcs(&xr[i0]);
        __stcs(&orr[i0], a);
        s0 += a.x + a.y + a.z + a.w;
        quad_max(a, i0 << 2, mval, midx);
    }

    float sum = (s0 + s1) + (s2 + s3);
    #pragma unroll
    for (int off = 16; off > 0; off >>= 1) {
        sum += __shfl_down_sync(0xffffffffu, sum, off);
        float ov = __shfl_down_sync(0xffffffffu, mval, off);
        int   oi = __shfl_down_sync(0xffffffffu, midx, off);
        if (ov > mval || (ov == mval && oi < midx)) { mval = ov; midx = oi; }
    }
    if (lane == 0) {
        g_sums[row] = sum;
        g_amax[row] = midx;
    }
}

// ---------------------------------------------------------------------------
// K2: one block per batch. PDL: prefetch weight slices into registers BEFORE
// the grid dependency sync (overlaps K1's drain), then SE + exact top-38,
// emitting packed task descriptors {row, aidx, lam}.
// ---------------------------------------------------------------------------
__global__ __launch_bounds__(256) void k2_se_topk(const float* __restrict__ w1,
                                                  const float* __restrict__ w2) {
    const int b = blockIdx.x;
    const int t = threadIdx.x;
    const int d    = t >> 4;
    const int part = t & 15;
    const int c0   = part * 16;

    // Prefetch weights (independent of K1) before the dependency sync.
    float w1v[16], w2v[16];
    #pragma unroll
    for (int k = 0; k < 16; k++) w1v[k] = __ldg(&w1[d * CC + c0 + k]);
    #pragma unroll
    for (int k = 0; k < 16; k++) w2v[k] = __ldg(&w2[t * 16 + k]);

    cudaGridDependencySynchronize();   // K1's g_sums/g_amax now visible

    __shared__ float s_pooled[CC];
    __shared__ float s_hidden[16];
    __shared__ float s_M[CC];

    s_pooled[t] = g_sums[b * CC + t] * (1.0f / (float)HW);
    __syncthreads();

    // fc1: 16-thread group per hidden unit, shfl-xor reduce within group
    {
        float acc = 0.0f;
        #pragma unroll
        for (int k = 0; k < 16; k++) acc += s_pooled[c0 + k] * w1v[k];
        #pragma unroll
        for (int off = 8; off > 0; off >>= 1)
            acc += __shfl_xor_sync(0xffffffffu, acc, off);
        if (part == 0) s_hidden[d] = fmaxf(acc, 0.0f);
    }
    __syncthreads();

    // fc2 + sigmoid
    {
        float acc = 0.0f;
        #pragma unroll
        for (int k = 0; k < 16; k++) acc += s_hidden[k] * w2v[k];
        s_M[t] = 1.0f / (1.0f + expf(-acc));
    }
    __syncthreads();

    const float m = s_M[t];
    int cnt = 0;
    for (int j = 0; j < CC; j++) {
        const float mj = s_M[j];
        cnt += (mj > m) || (mj == m && j < t);
    }
    if (cnt < TOPK) {
        const int row  = b * CC + t;
        const int aidx = g_amax[row];
        const int mh = aidx / WW;
        const int mw = aidx % WW;
        const int h1  = max(mh - 2, 0), h2  = min(mh + 2, HH - 1);
        const int w1b = max(mw - 2, 0), w2b = min(mw + 2, WW - 1);
        const int box = (h2 - h1 + 1) * (w2b - w1b + 1);
        const float lam = (float)HW / (float)(HW - box);
        g_task[b * TOPK + cnt] = make_int4(row, aidx, __float_as_int(lam), 0);
    }
}

// ---------------------------------------------------------------------------
// K3: 128-thread blocks, 4 warps/block, quarter-row per warp, all loads
// front-batched (MLP ~7). Single packed-task load (no dependent chain).
// ---------------------------------------------------------------------------
__global__ __launch_bounds__(128) void k3_apply(const float* __restrict__ x,
                                                float* __restrict__ out) {
    cudaGridDependencySynchronize();   // K2's g_task now visible

    const int warp = threadIdx.x >> 5;
    const int lane = threadIdx.x & 31;
    const int gw   = blockIdx.x * 4 + warp;
    const int sel  = gw >> 2;
    const int part = gw & 3;

    const int4 tk  = g_task[sel];
    const int row  = tk.x;
    const int aidx = tk.y;
    const float lam = __int_as_float(tk.z);
    const int mh = aidx / WW;
    const int mw = aidx % WW;
    const int h1  = max(mh - 2, 0), h2  = min(mh + 2, HH - 1);
    const int w1b = max(mw - 2, 0), w2b = min(mw + 2, WW - 1);

    const float4* __restrict__ xr  = (const float4*)(x   + (size_t)row * HW);
    float4*       __restrict__ orr = (float4*)      (out + (size_t)row * HW);
    const int q0 = part * QW;                 // [q0, q0+196)

    float4 v[6];
    #pragma unroll
    for (int k = 0; k < 6; k++) v[k] = __ldcs(&xr[q0 + k * 32 + lane]);
    float4 vt;
    const bool has_tail = (lane < 4);
    if (has_tail) vt = __ldcs(&xr[q0 + 192 + lane]);

    #pragma unroll
    for (int k = 0; k < 6; k++) {
        const int i0 = q0 + k * 32 + lane;
        const int p  = i0 << 2;
        const int r  = p / WW;
        const int c0 = p % WW;                // WW % 4 == 0: same image row
        const bool rin = (r >= h1) && (r <= h2);
        float4 o;
        o.x = (rin && c0     >= w1b && c0     <= w2b) ? 0.0f : v[k].x * lam;
        o.y = (rin && c0 + 1 >= w1b && c0 + 1 <= w2b) ? 0.0f : v[k].y * lam;
        o.z = (rin && c0 + 2 >= w1b && c0 + 2 <= w2b) ? 0.0f : v[k].z * lam;
        o.w = (rin && c0 + 3 >= w1b && c0 + 3 <= w2b) ? 0.0f : v[k].w * lam;
        __stcs(&orr[i0], o);
    }
    if (has_tail) {
        const int i0 = q0 + 192 + lane;
        const int p  = i0 << 2;
        const int r  = p / WW;
        const int c0 = p % WW;
        const bool rin = (r >= h1) && (r <= h2);
        float4 o;
        o.x = (rin && c0     >= w1b && c0     <= w2b) ? 0.0f : vt.x * lam;
        o.y = (rin && c0 + 1 >= w1b && c0 + 1 <= w2b) ? 0.0f : vt.y * lam;
        o.z = (rin && c0 + 2 >= w1b && c0 + 2 <= w2b) ? 0.0f : vt.z * lam;
        o.w = (rin && c0 + 3 >= w1b && c0 + 3 <= w2b) ? 0.0f : vt.w * lam;
        __stcs(&orr[i0], o);
    }
}

// ---------------------------------------------------------------------------
extern "C" void kernel_launch(void* const* d_in, const int* in_sizes, int n_in,
                              void* d_out, int out_size) {
    const float* x  = (const float*)d_in[0];
    const float* w1 = (const float*)d_in[1];
    const float* w2 = (const float*)d_in[2];
    float* out = (float*)d_out;

    k1_reduce_copy<<<NROWS / 8, 256>>>(x, out);   // 2048 blocks

    cudaLaunchAttribute attr[1];
    attr[0].id = cudaLaunchAttributeProgrammaticStreamSerialization;
    attr[0].val.programmaticStreamSerializationAllowed = 1;

    {   // K2 with PDL
        cudaLaunchConfig_t cfg = {};
        cfg.gridDim  = dim3(BB, 1, 1);
        cfg.blockDim = dim3(256, 1, 1);
        cfg.attrs    = attr;
        cfg.numAttrs = 1;
        cudaLaunchKernelEx(&cfg, k2_se_topk, w1, w2);
    }
    {   // K3 with PDL
        cudaLaunchConfig_t cfg = {};
        cfg.gridDim  = dim3(NSEL, 1, 1);          // 2432 blocks of 128
        cfg.blockDim = dim3(128, 1, 1);
        cfg.attrs    = attr;
        cfg.numAttrs = 1;
        cudaLaunchKernelEx(&cfg, k3_apply, x, out);
    }
}